// round 12
// baseline (speedup 1.0000x reference)
#include <cuda_runtime.h>
#include <cuda_bf16.h>
#include <cstdint>
#include <math.h>

#define BB 32
#define TT 1000
#define HH 1024
#define C2 2048
#define RGRID 128
#define RTHREADS 256
#define RPAD 1032            // bf16 row stride: 2064 B, 16 mod 128 -> conflict-free ldmatrix

// ---------------- device scratch (static, no allocation) ----------------
__device__ float g_w[BB * TT * C2];      // 262 MB: projected gates (pre-BN), reused per layer
__device__ float g_h1[BB * TT * HH];     // 131 MB: layer-1 outputs
__device__ float g_h[BB * HH];           // current hidden state (fp32)
__device__ __nv_bfloat16 g_hh[BB * HH];  // hidden state bf16-hi
__device__ __nv_bfloat16 g_hl[BB * HH];  // hidden state bf16-lo (residual)
__device__ float g_colsum[C2];
__device__ float g_colsumsq[C2];
__device__ float g_scale[C2];
__device__ float g_bias[C2];
__device__ float g_rowsum[2][BB];        // ping-pong LN accumulators
__device__ float g_rowsumsq[2][BB];
__device__ unsigned g_bar_count;

// ---------------- init: zero all per-layer state ----------------
__global__ void init_kernel() {
    int tid = blockIdx.x * blockDim.x + threadIdx.x;
    if (tid == 0) g_bar_count = 0u;
    if (tid < C2) { g_colsum[tid] = 0.f; g_colsumsq[tid] = 0.f; }
    if (tid < 2 * BB) {
        (&g_rowsum[0][0])[tid] = 0.f;
        (&g_rowsumsq[0][0])[tid] = 0.f;
    }
    for (int i = tid; i < BB * HH; i += gridDim.x * blockDim.x) {
        g_h[i] = 0.f;
        g_hh[i] = __float2bfloat16(0.f);
        g_hl[i] = __float2bfloat16(0.f);
    }
}

// ---------------- projection GEMM: g_w[n][c] = sum_k A[n][k] * W[c][k] ----------------
__global__ __launch_bounds__(256)
void proj_gemm_kernel(const float* __restrict__ Ain, const float* __restrict__ W,
                      int K, int useH1) {
    const float* __restrict__ A = useH1 ? g_h1 : Ain;
    __shared__ float As[16][128];
    __shared__ float Ws[16][128];
    const int tid = threadIdx.x;
    const int bn = blockIdx.x * 128;
    const int bm = blockIdx.y * 128;
    const int tx = tid & 15;
    const int ty = tid >> 4;
    const int lr = tid >> 2;
    const int lk = (tid & 3) << 2;

    float acc[8][8];
#pragma unroll
    for (int i = 0; i < 8; i++)
#pragma unroll
        for (int j = 0; j < 8; j++) acc[i][j] = 0.f;

    for (int k0 = 0; k0 < K; k0 += 16) {
        float4 a0 = *(const float4*)&A[(bm + lr) * K + k0 + lk];
        float4 a1 = *(const float4*)&A[(bm + 64 + lr) * K + k0 + lk];
        float4 w0 = *(const float4*)&W[(bn + lr) * K + k0 + lk];
        float4 w1 = *(const float4*)&W[(bn + 64 + lr) * K + k0 + lk];
        __syncthreads();
        As[lk + 0][lr] = a0.x; As[lk + 1][lr] = a0.y; As[lk + 2][lr] = a0.z; As[lk + 3][lr] = a0.w;
        As[lk + 0][64 + lr] = a1.x; As[lk + 1][64 + lr] = a1.y; As[lk + 2][64 + lr] = a1.z; As[lk + 3][64 + lr] = a1.w;
        Ws[lk + 0][lr] = w0.x; Ws[lk + 1][lr] = w0.y; Ws[lk + 2][lr] = w0.z; Ws[lk + 3][lr] = w0.w;
        Ws[lk + 0][64 + lr] = w1.x; Ws[lk + 1][64 + lr] = w1.y; Ws[lk + 2][64 + lr] = w1.z; Ws[lk + 3][64 + lr] = w1.w;
        __syncthreads();
#pragma unroll
        for (int kk = 0; kk < 16; kk++) {
            float4 x0 = *(const float4*)&As[kk][tx * 4];
            float4 x1 = *(const float4*)&As[kk][64 + tx * 4];
            float4 y0 = *(const float4*)&Ws[kk][ty * 4];
            float4 y1 = *(const float4*)&Ws[kk][64 + ty * 4];
            float xs[8] = {x0.x, x0.y, x0.z, x0.w, x1.x, x1.y, x1.z, x1.w};
            float ys[8] = {y0.x, y0.y, y0.z, y0.w, y1.x, y1.y, y1.z, y1.w};
#pragma unroll
            for (int i = 0; i < 8; i++)
#pragma unroll
                for (int j = 0; j < 8; j++) acc[i][j] = fmaf(xs[i], ys[j], acc[i][j]);
        }
    }

#pragma unroll
    for (int i = 0; i < 8; i++) {
        int row = bm + ((i < 4) ? (tx * 4 + i) : (64 + tx * 4 + i - 4));
        float4 v0 = make_float4(acc[i][0], acc[i][1], acc[i][2], acc[i][3]);
        float4 v1 = make_float4(acc[i][4], acc[i][5], acc[i][6], acc[i][7]);
        *(float4*)&g_w[row * C2 + bn + ty * 4] = v0;
        *(float4*)&g_w[row * C2 + bn + 64 + ty * 4] = v1;
    }
}

// ---------------- BN column stats over 32000 rows ----------------
__global__ void bn_stats_kernel() {
    int c = blockIdx.x * 256 + threadIdx.x;
    int n0 = blockIdx.y * (BB * TT / 64);
    float s = 0.f, ss = 0.f;
    for (int n = 0; n < BB * TT / 64; n++) {
        float v = g_w[(n0 + n) * C2 + c];
        s += v;
        ss = fmaf(v, v, ss);
    }
    atomicAdd(&g_colsum[c], s);
    atomicAdd(&g_colsumsq[c], ss);
}

__global__ void bn_finalize_kernel(const float* __restrict__ gam, const float* __restrict__ bet) {
    int c = blockIdx.x * 256 + threadIdx.x;
    float inv_n = 1.f / (float)(BB * TT);
    float mu = g_colsum[c] * inv_n;
    float var = g_colsumsq[c] * inv_n - mu * mu;
    float s = gam[c] * rsqrtf(var + 1e-5f);
    g_scale[c] = s;
    g_bias[c] = bet[c] - mu * s;
}

// ---------------- grid barrier (monotonic counter) ----------------
__device__ __forceinline__ void grid_barrier(unsigned tgt) {
    __syncthreads();
    if (threadIdx.x == 0) {
        __threadfence();
        atomicAdd(&g_bar_count, 1u);
        while (*(volatile unsigned*)&g_bar_count < tgt) {}
        __threadfence();
    }
    __syncthreads();
}

// ---------------- mma helpers ----------------
__device__ __forceinline__ uint32_t s2u(const void* p) {
    return (uint32_t)__cvta_generic_to_shared(p);
}

#define LDSM_X4(r0, r1, r2, r3, a) \
    asm volatile("ldmatrix.sync.aligned.m8n8.x4.shared.b16 {%0,%1,%2,%3}, [%4];" \
                 : "=r"(r0), "=r"(r1), "=r"(r2), "=r"(r3) : "r"(a))

#define LDSM_X2(r0, r1, a) \
    asm volatile("ldmatrix.sync.aligned.m8n8.x2.shared.b16 {%0,%1}, [%2];" \
                 : "=r"(r0), "=r"(r1) : "r"(a))

#define MMA_BF16(c, a0, a1, a2, a3, b0, b1) \
    asm volatile("mma.sync.aligned.m16n8k16.row.col.f32.bf16.bf16.f32 " \
                 "{%0,%1,%2,%3}, {%4,%5,%6,%7}, {%8,%9}, {%0,%1,%2,%3};" \
                 : "+f"(c[0]), "+f"(c[1]), "+f"(c[2]), "+f"(c[3]) \
                 : "r"(a0), "r"(a1), "r"(a2), "r"(a3), "r"(b0), "r"(b1))

// ---------------- persistent recurrence kernel ----------------
// 128 CTAs x 256 threads, 1 CTA/SM. CTA cid owns gate rows j0..j0+7 (a) and
// H+j0..H+j0+7 (z). Per-step GEMM uh[32b][16r] (K=1024) runs on tensor cores
// in 2-term-split bf16 (3 MMAs per tile pair), warps partition K (128 each),
// cross-warp reduce via SMEM partials.
__global__ __launch_bounds__(RTHREADS, 1)
void recurrence_kernel(const float* __restrict__ U, float* __restrict__ out_ext, int toH1) {
    float* __restrict__ out = toH1 ? g_h1 : out_ext;
    extern __shared__ char smem[];
    __nv_bfloat16* Ush = (__nv_bfloat16*)smem;                  // [16][1032]
    __nv_bfloat16* Usl = (__nv_bfloat16*)(smem + 33024);        // [16][1032]
    __nv_bfloat16* hsh = (__nv_bfloat16*)(smem + 66048);        // [32][1032]
    __nv_bfloat16* hsl = (__nv_bfloat16*)(smem + 132096);       // [32][1032]
    float* part = (float*)(smem + 198144);                      // [8][512]
    float* uhs  = (float*)(smem + 214528);                      // [32][17]
    float* scs  = (float*)(smem + 216704);                      // [16]
    float* bis  = (float*)(smem + 216768);                      // [16]

    const int tid = threadIdx.x;
    const int cid = blockIdx.x;
    const int j0 = cid * 8;
    const int lane = tid & 31;
    const int wid = tid >> 5;
    const int pb = tid >> 3;           // phase-B batch
    const int pj = tid & 7;            // phase-B feature within chunk

    // one-time: load + split U slice (rows 0-7 = a gate j0.., rows 8-15 = z gate H+j0..)
    for (int i = tid; i < 16 * 1024; i += RTHREADS) {
        int rl = i >> 10, kk = i & 1023;
        int gr = (rl < 8) ? (j0 + rl) : (HH + j0 + rl - 8);
        float v = U[gr * 1024 + kk];
        __nv_bfloat16 vh = __float2bfloat16(v);
        Ush[rl * RPAD + kk] = vh;
        Usl[rl * RPAD + kk] = __float2bfloat16(v - __bfloat162float(vh));
    }
    if (tid < 16) {
        int c = (tid < 8) ? (j0 + tid) : (HH + j0 + (tid - 8));
        scs[tid] = g_scale[c];
        bis[tid] = g_bias[c];
    }

    // ldmatrix base addresses (advance by 32 B per k-chunk of 16)
    const int kbase = wid * 128;
    const int rA = lane & 15;
    const int cA = (lane >> 4) << 3;
    const int rB = lane & 7;
    const int cB = ((lane >> 3) & 1) << 3;
    const uint32_t aAh0_b = s2u(hsh) + (uint32_t)(rA * RPAD + kbase + cA) * 2;
    const uint32_t aAl0_b = s2u(hsl) + (uint32_t)(rA * RPAD + kbase + cA) * 2;
    const uint32_t aBh0_b = s2u(Ush) + (uint32_t)(rB * RPAD + kbase + cB) * 2;
    const uint32_t aBl0_b = s2u(Usl) + (uint32_t)(rB * RPAD + kbase + cB) * 2;
    const uint32_t mOff = 16 * RPAD * 2;   // +16 batch rows
    const uint32_t nOff = 8 * RPAD * 2;    // +8 gate rows

    unsigned epoch = 0;

    for (int t = 0; t < TT; t++) {
        const int par = t & 1;
        // prefetch this step's w and own old-h (consumed in phase B, after barrier)
        float wa = g_w[(pb * TT + t) * C2 + j0 + pj];
        float wz = g_w[(pb * TT + t) * C2 + HH + j0 + pj];
        float hown = __ldcg(&g_h[pb * HH + j0 + pj]);

        // broadcast-load pre-split h (bf16 hi/lo) into padded SMEM
        for (int c = tid; c < 4096; c += RTHREADS) {
            int row = c >> 7, col = (c & 127) << 3;
            uint4 vh = __ldcg((const uint4*)&g_hh[(row << 10) + col]);
            uint4 vl = __ldcg((const uint4*)&g_hl[(row << 10) + col]);
            *(uint4*)&hsh[row * RPAD + col] = vh;
            *(uint4*)&hsl[row * RPAD + col] = vl;
        }
        __syncthreads();

        // tensor-core GEMM: acc[mt][nt] = D tiles of uh[32][16] over this warp's K slice
        float acc[2][2][4];
#pragma unroll
        for (int i = 0; i < 2; i++)
#pragma unroll
            for (int j = 0; j < 2; j++) {
                acc[i][j][0] = 0.f; acc[i][j][1] = 0.f;
                acc[i][j][2] = 0.f; acc[i][j][3] = 0.f;
            }

#pragma unroll
        for (int kc = 0; kc < 8; kc++) {
            const uint32_t d = kc * 32;
            uint32_t ah0[4], ah1[4], al0[4], al1[4];
            uint32_t bh0[2], bh1[2], bl0[2], bl1[2];
            LDSM_X4(ah0[0], ah0[1], ah0[2], ah0[3], aAh0_b + d);
            LDSM_X4(ah1[0], ah1[1], ah1[2], ah1[3], aAh0_b + mOff + d);
            LDSM_X4(al0[0], al0[1], al0[2], al0[3], aAl0_b + d);
            LDSM_X4(al1[0], al1[1], al1[2], al1[3], aAl0_b + mOff + d);
            LDSM_X2(bh0[0], bh0[1], aBh0_b + d);
            LDSM_X2(bh1[0], bh1[1], aBh0_b + nOff + d);
            LDSM_X2(bl0[0], bl0[1], aBl0_b + d);
            LDSM_X2(bl1[0], bl1[1], aBl0_b + nOff + d);

            MMA_BF16(acc[0][0], ah0[0], ah0[1], ah0[2], ah0[3], bh0[0], bh0[1]);
            MMA_BF16(acc[0][1], ah0[0], ah0[1], ah0[2], ah0[3], bh1[0], bh1[1]);
            MMA_BF16(acc[1][0], ah1[0], ah1[1], ah1[2], ah1[3], bh0[0], bh0[1]);
            MMA_BF16(acc[1][1], ah1[0], ah1[1], ah1[2], ah1[3], bh1[0], bh1[1]);
            // cross terms: hi*lo + lo*hi
            MMA_BF16(acc[0][0], ah0[0], ah0[1], ah0[2], ah0[3], bl0[0], bl0[1]);
            MMA_BF16(acc[0][1], ah0[0], ah0[1], ah0[2], ah0[3], bl1[0], bl1[1]);
            MMA_BF16(acc[1][0], ah1[0], ah1[1], ah1[2], ah1[3], bl0[0], bl0[1]);
            MMA_BF16(acc[1][1], ah1[0], ah1[1], ah1[2], ah1[3], bl1[0], bl1[1]);
            MMA_BF16(acc[0][0], al0[0], al0[1], al0[2], al0[3], bh0[0], bh0[1]);
            MMA_BF16(acc[0][1], al0[0], al0[1], al0[2], al0[3], bh1[0], bh1[1]);
            MMA_BF16(acc[1][0], al1[0], al1[1], al1[2], al1[3], bh0[0], bh0[1]);
            MMA_BF16(acc[1][1], al1[0], al1[1], al1[2], al1[3], bh1[0], bh1[1]);
        }

        // scatter warp partials: D frag mapping (b = m, r = n)
        {
            float* myp = part + wid * 512;
            const int br = lane >> 2;
            const int cc = (lane & 3) * 2;
#pragma unroll
            for (int mt = 0; mt < 2; mt++)
#pragma unroll
                for (int nt = 0; nt < 2; nt++) {
                    int b = mt * 16 + br;
                    int r = nt * 8 + cc;
                    *(float2*)&myp[b * 16 + r] =
                        make_float2(acc[mt][nt][0], acc[mt][nt][1]);
                    *(float2*)&myp[(b + 8) * 16 + r] =
                        make_float2(acc[mt][nt][2], acc[mt][nt][3]);
                }
        }
        __syncthreads();

        // 8-way cross-warp reduce (coalesced) + fused LN row-stat atomics
        {
            const int o1 = tid, o2 = tid + 256;
            float v1 = 0.f, v2 = 0.f;
#pragma unroll
            for (int w = 0; w < 8; w++) {
                v1 += part[w * 512 + o1];
                v2 += part[w * 512 + o2];
            }
            uhs[(o1 >> 4) * 17 + (o1 & 15)] = v1;
            uhs[(o2 >> 4) * 17 + (o2 & 15)] = v2;
            float s1 = v1, q1 = v1 * v1, s2 = v2, q2 = v2 * v2;
#pragma unroll
            for (int off = 8; off; off >>= 1) {
                s1 += __shfl_xor_sync(0xffffffffu, s1, off);
                q1 += __shfl_xor_sync(0xffffffffu, q1, off);
                s2 += __shfl_xor_sync(0xffffffffu, s2, off);
                q2 += __shfl_xor_sync(0xffffffffu, q2, off);
            }
            if ((lane & 15) == 0) {
                atomicAdd(&g_rowsum[par][o1 >> 4], s1);
                atomicAdd(&g_rowsumsq[par][o1 >> 4], q1);
                atomicAdd(&g_rowsum[par][o2 >> 4], s2);
                atomicAdd(&g_rowsumsq[par][o2 >> 4], q2);
            }
        }
        // one CTA zeroes the other parity's accumulators for the next step
        if (cid == 0 && wid == 1) {
            g_rowsum[1 - par][lane] = 0.f;
            g_rowsumsq[1 - par][lane] = 0.f;
        }

        grid_barrier((++epoch) * RGRID);

        // phase B: LN + gates + state update
        {
            float m = __ldcg(&g_rowsum[par][pb]) * (1.f / 2048.f);
            float ms = __ldcg(&g_rowsumsq[par][pb]) * (1.f / 2048.f);
            float inv = rsqrtf(ms - m * m + 1e-5f);
            float ga = fmaf(wa, scs[pj], bis[pj]) + (uhs[pb * 17 + pj] - m) * inv;
            float gz = fmaf(wz, scs[8 + pj], bis[8 + pj]) + (uhs[pb * 17 + 8 + pj] - m) * inv;
            float z = 1.f / (1.f + expf(-gz));
            float a = fmaxf(ga, 0.f);
            float hn = fmaf(z, hown, (1.f - z) * a);
            int gi = pb * HH + j0 + pj;
            g_h[gi] = hn;
            __nv_bfloat16 hh = __float2bfloat16(hn);
            g_hh[gi] = hh;
            g_hl[gi] = __float2bfloat16(hn - __bfloat162float(hh));
            out[(pb * TT + t) * HH + j0 + pj] = hn;
        }

        grid_barrier((++epoch) * RGRID);
    }
}

// ---------------- launch ----------------
extern "C" void kernel_launch(void* const* d_in, const int* in_sizes, int n_in,
                              void* d_out, int out_size) {
    const float* x  = (const float*)d_in[0];
    const float* W1 = (const float*)d_in[1];
    const float* U1 = (const float*)d_in[2];
    const float* g1 = (const float*)d_in[3];
    const float* b1 = (const float*)d_in[4];
    const float* W2 = (const float*)d_in[5];
    const float* U2 = (const float*)d_in[6];
    const float* g2 = (const float*)d_in[7];
    const float* b2 = (const float*)d_in[8];
    float* out = (float*)d_out;

    const int RSMEM = 216832;
    cudaFuncSetAttribute(recurrence_kernel, cudaFuncAttributeMaxDynamicSharedMemorySize, RSMEM);

    // ---- layer 1 ----
    init_kernel<<<32, 1024>>>();
    proj_gemm_kernel<<<dim3(16, 250), 256>>>(x, W1, 80, 0);
    bn_stats_kernel<<<dim3(8, 64), 256>>>();
    bn_finalize_kernel<<<8, 256>>>(g1, b1);
    recurrence_kernel<<<RGRID, RTHREADS, RSMEM>>>(U1, nullptr, 1);

    // ---- layer 2 ----
    init_kernel<<<32, 1024>>>();
    proj_gemm_kernel<<<dim3(16, 250), 256>>>(nullptr, W2, 1024, 1);
    bn_stats_kernel<<<dim3(8, 64), 256>>>();
    bn_finalize_kernel<<<8, 256>>>(g2, b2);
    recurrence_kernel<<<RGRID, RTHREADS, RSMEM>>>(U2, out, 0);
}

// round 13
// speedup vs baseline: 1.1804x; 1.1804x over previous
#include <cuda_runtime.h>
#include <cuda_bf16.h>
#include <cstdint>
#include <math.h>

#define BB 32
#define TT 1000
#define HH 1024
#define C2 2048
#define RGRID 128
#define RTHREADS 256
#define APAD 40   // bf16 elems per SMEM row (32 data + 8 pad) = 80 B -> conflict-free ldmatrix

// ---------------- device scratch (static, no allocation) ----------------
__device__ float g_w[BB * TT * C2];      // 262 MB: projected gates (pre-BN), reused per layer
__device__ float g_h1[BB * TT * HH];     // 131 MB: layer-1 outputs
__device__ float g_h[BB * HH];           // current hidden state
__device__ float g_colsum[C2];
__device__ float g_colsumsq[C2];
__device__ float g_scale[C2];
__device__ float g_bias[C2];
__device__ float g_rowsum[2][BB];        // ping-pong LN accumulators
__device__ float g_rowsumsq[2][BB];
__device__ unsigned g_bar_count;

// ---------------- init: zero all per-layer state ----------------
__global__ void init_kernel() {
    int tid = blockIdx.x * blockDim.x + threadIdx.x;
    if (tid == 0) g_bar_count = 0u;
    if (tid < C2) { g_colsum[tid] = 0.f; g_colsumsq[tid] = 0.f; }
    if (tid < 2 * BB) {
        (&g_rowsum[0][0])[tid] = 0.f;
        (&g_rowsumsq[0][0])[tid] = 0.f;
    }
    for (int i = tid; i < BB * HH; i += gridDim.x * blockDim.x) g_h[i] = 0.f;
}

// ---------------- mma helpers ----------------
__device__ __forceinline__ uint32_t s2u(const void* p) {
    return (uint32_t)__cvta_generic_to_shared(p);
}

#define LDSM_X4(r0, r1, r2, r3, a) \
    asm volatile("ldmatrix.sync.aligned.m8n8.x4.shared.b16 {%0,%1,%2,%3}, [%4];" \
                 : "=r"(r0), "=r"(r1), "=r"(r2), "=r"(r3) : "r"(a))

#define MMA_BF16(c, a0, a1, a2, a3, b0, b1) \
    asm volatile("mma.sync.aligned.m16n8k16.row.col.f32.bf16.bf16.f32 " \
                 "{%0,%1,%2,%3}, {%4,%5,%6,%7}, {%8,%9}, {%0,%1,%2,%3};" \
                 : "+f"(c[0]), "+f"(c[1]), "+f"(c[2]), "+f"(c[3]) \
                 : "r"(a0), "r"(a1), "r"(a2), "r"(a3), "r"(b0), "r"(b1))

// ---------------- projection GEMM (tensor cores, split-bf16) ----------------
// g_w[n][c] = sum_k A[n][k] * W[c][k] in ~fp32 accuracy via 2-term bf16 split:
// A = Ah + Al, W = Bh + Bl; D += Ah*Bh + Ah*Bl + Al*Bh (drop Al*Bl, ~2^-16 rel).
// Tiles: BM=128, BN=128, BK=32; 256 threads = 8 warps as 2(m) x 4(n), warp tile 64x32.
__global__ __launch_bounds__(256)
void proj_mma_kernel(const float* __restrict__ Ain, const float* __restrict__ W,
                     int K, int useH1) {
    const float* __restrict__ A = useH1 ? g_h1 : Ain;
    __shared__ __nv_bfloat16 Ah[128 * APAD], Al[128 * APAD];
    __shared__ __nv_bfloat16 Bh[128 * APAD], Bl[128 * APAD];

    const int tid = threadIdx.x;
    const int lane = tid & 31;
    const int wid = tid >> 5;
    const int wm = (wid & 1) * 64;     // warp m offset
    const int wn = (wid >> 1) * 32;    // warp n offset
    const int bn = blockIdx.x * 128;
    const int bm = blockIdx.y * 128;

    float acc[4][4][4];
#pragma unroll
    for (int mt = 0; mt < 4; mt++)
#pragma unroll
        for (int nt = 0; nt < 4; nt++) {
            acc[mt][nt][0] = 0.f; acc[mt][nt][1] = 0.f;
            acc[mt][nt][2] = 0.f; acc[mt][nt][3] = 0.f;
        }

    // ldmatrix addresses (within-tile, element offsets computed per use)
    const int arow = lane & 15;
    const int acol = (lane >> 4) << 3;
    const int brow = (lane & 7) + ((lane >> 4) << 3);
    const int bcol = ((lane >> 3) & 1) << 3;
    const uint32_t sAh = s2u(Ah), sAl = s2u(Al), sBh = s2u(Bh), sBl = s2u(Bl);

    for (int k0 = 0; k0 < K; k0 += 32) {
        // ---- stage: global fp32 -> regs ----
        float4 av[4], bv[4];
#pragma unroll
        for (int i = 0; i < 4; i++) {
            int idx = i * 256 + tid;
            int row = idx >> 3, lk = (idx & 7) << 2;
            bool ok = (k0 + lk) < K;   // K is a multiple of 4, so whole float4 valid
            av[i] = ok ? *(const float4*)&A[(bm + row) * K + k0 + lk]
                       : make_float4(0.f, 0.f, 0.f, 0.f);
            bv[i] = ok ? *(const float4*)&W[(bn + row) * K + k0 + lk]
                       : make_float4(0.f, 0.f, 0.f, 0.f);
        }
        __syncthreads();
        // ---- split fp32 -> bf16 hi/lo, store to SMEM (packed 8B stores) ----
#pragma unroll
        for (int i = 0; i < 4; i++) {
            int idx = i * 256 + tid;
            int row = idx >> 3, lk = (idx & 7) << 2;
            float va[4] = {av[i].x, av[i].y, av[i].z, av[i].w};
            float vb[4] = {bv[i].x, bv[i].y, bv[i].z, bv[i].w};
            __nv_bfloat16 h0[4], l0[4], h1[4], l1[4];
#pragma unroll
            for (int j = 0; j < 4; j++) {
                h0[j] = __float2bfloat16(va[j]);
                l0[j] = __float2bfloat16(va[j] - __bfloat162float(h0[j]));
                h1[j] = __float2bfloat16(vb[j]);
                l1[j] = __float2bfloat16(vb[j] - __bfloat162float(h1[j]));
            }
            *(uint2*)&Ah[row * APAD + lk] = *(uint2*)h0;
            *(uint2*)&Al[row * APAD + lk] = *(uint2*)l0;
            *(uint2*)&Bh[row * APAD + lk] = *(uint2*)h1;
            *(uint2*)&Bl[row * APAD + lk] = *(uint2*)l1;
        }
        __syncthreads();

        // ---- compute: 2 x k16 steps ----
#pragma unroll
        for (int ks = 0; ks < 32; ks += 16) {
            uint32_t ah[4][4], al[4][4], bh[4][2], bl[4][2];
#pragma unroll
            for (int mt = 0; mt < 4; mt++) {
                uint32_t off = (uint32_t)((wm + mt * 16 + arow) * APAD + ks + acol) * 2;
                LDSM_X4(ah[mt][0], ah[mt][1], ah[mt][2], ah[mt][3], sAh + off);
                LDSM_X4(al[mt][0], al[mt][1], al[mt][2], al[mt][3], sAl + off);
            }
#pragma unroll
            for (int nt2 = 0; nt2 < 2; nt2++) {
                uint32_t off = (uint32_t)((wn + nt2 * 16 + brow) * APAD + ks + bcol) * 2;
                uint32_t r0, r1, r2, r3;
                LDSM_X4(r0, r1, r2, r3, sBh + off);
                bh[nt2 * 2][0] = r0; bh[nt2 * 2][1] = r1;
                bh[nt2 * 2 + 1][0] = r2; bh[nt2 * 2 + 1][1] = r3;
                LDSM_X4(r0, r1, r2, r3, sBl + off);
                bl[nt2 * 2][0] = r0; bl[nt2 * 2][1] = r1;
                bl[nt2 * 2 + 1][0] = r2; bl[nt2 * 2 + 1][1] = r3;
            }
#pragma unroll
            for (int mt = 0; mt < 4; mt++)
#pragma unroll
                for (int nt = 0; nt < 4; nt++) {
                    MMA_BF16(acc[mt][nt], ah[mt][0], ah[mt][1], ah[mt][2], ah[mt][3],
                             bh[nt][0], bh[nt][1]);
                    MMA_BF16(acc[mt][nt], ah[mt][0], ah[mt][1], ah[mt][2], ah[mt][3],
                             bl[nt][0], bl[nt][1]);
                    MMA_BF16(acc[mt][nt], al[mt][0], al[mt][1], al[mt][2], al[mt][3],
                             bh[nt][0], bh[nt][1]);
                }
        }
        __syncthreads();
    }

    // ---- epilogue: D frag (row = lane>>2 [+8], col = (lane&3)*2) ----
#pragma unroll
    for (int mt = 0; mt < 4; mt++) {
        int row = bm + wm + mt * 16 + (lane >> 2);
#pragma unroll
        for (int nt = 0; nt < 4; nt++) {
            int col = bn + wn + nt * 8 + (lane & 3) * 2;
            *(float2*)&g_w[row * C2 + col] = make_float2(acc[mt][nt][0], acc[mt][nt][1]);
            *(float2*)&g_w[(row + 8) * C2 + col] = make_float2(acc[mt][nt][2], acc[mt][nt][3]);
        }
    }
}

// ---------------- BN column stats over 32000 rows ----------------
__global__ void bn_stats_kernel() {
    int c = blockIdx.x * 256 + threadIdx.x;
    int n0 = blockIdx.y * (BB * TT / 64);
    float s = 0.f, ss = 0.f;
    for (int n = 0; n < BB * TT / 64; n++) {
        float v = g_w[(n0 + n) * C2 + c];
        s += v;
        ss = fmaf(v, v, ss);
    }
    atomicAdd(&g_colsum[c], s);
    atomicAdd(&g_colsumsq[c], ss);
}

__global__ void bn_finalize_kernel(const float* __restrict__ gam, const float* __restrict__ bet) {
    int c = blockIdx.x * 256 + threadIdx.x;
    float inv_n = 1.f / (float)(BB * TT);
    float mu = g_colsum[c] * inv_n;
    float var = g_colsumsq[c] * inv_n - mu * mu;
    float s = gam[c] * rsqrtf(var + 1e-5f);
    g_scale[c] = s;
    g_bias[c] = bet[c] - mu * s;
}

// ---------------- grid barrier (monotonic counter) ----------------
__device__ __forceinline__ void grid_barrier(unsigned tgt) {
    __syncthreads();
    if (threadIdx.x == 0) {
        __threadfence();
        atomicAdd(&g_bar_count, 1u);
        while (*(volatile unsigned*)&g_bar_count < tgt) {}
        __threadfence();
    }
    __syncthreads();
}

// ---------------- persistent recurrence kernel (proven R7 FFMA version) ----------------
// 128 CTAs x 256 threads, 1 CTA/SM (SMEM-limited) -> all co-resident.
// CTA cid owns gate rows j0..j0+7 (a) and H+j0..H+j0+7 (z); keeps its 16 U rows in SMEM.
__global__ __launch_bounds__(RTHREADS, 1)
void recurrence_kernel(const float* __restrict__ U, float* __restrict__ out_ext, int toH1) {
    float* __restrict__ out = toH1 ? g_h1 : out_ext;
    extern __shared__ float smem[];
    float* Us = smem;                  // [16][1024]  64 KB
    float* hs = smem + 16 * 1024;      // [32][1024] 128 KB
    float* uhs = smem + 48 * 1024;     // [32][17]
    float* scs = uhs + 32 * 17;        // [16]
    float* bis = scs + 16;             // [16]

    const int tid = threadIdx.x;
    const int cid = blockIdx.x;
    const int j0 = cid * 8;
    const int lane = tid & 31;
    const int wid = tid >> 5;
    const int rw = (wid & 3) * 4;      // 4 local gate-rows per warp
    const int bb = (wid >> 2) * 16;    // 16 batches per warp half
    const int pb = tid >> 3;           // phase-B batch
    const int pj = tid & 7;            // phase-B j within chunk

    // one-time: load U slice + folded BN affine
    for (int i = tid; i < 16 * 256; i += RTHREADS) {
        int rl = i >> 8;
        int kk = (i & 255) << 2;
        int gr = (rl < 8) ? (j0 + rl) : (HH + j0 + rl - 8);
        *(float4*)&Us[rl * 1024 + kk] = *(const float4*)&U[gr * 1024 + kk];
    }
    if (tid < 16) {
        int c = (tid < 8) ? (j0 + tid) : (HH + j0 + (tid - 8));
        scs[tid] = g_scale[c];
        bis[tid] = g_bias[c];
    }

    unsigned epoch = 0;

    for (int t = 0; t < TT; t++) {
        const int par = t & 1;
        // prefetch this step's w early (independent of barrier/h)
        float wa = g_w[(pb * TT + t) * C2 + j0 + pj];
        float wz = g_w[(pb * TT + t) * C2 + HH + j0 + pj];

        // load full h into SMEM (L2-coherent reads)
        for (int i = tid * 4; i < BB * HH; i += RTHREADS * 4)
            *(float4*)&hs[i] = __ldcg((const float4*)&g_h[i]);
        __syncthreads();

        // GEMM: uh[b][r] = sum_k h[b][k] * Us[r][k]; lanes partition k
#pragma unroll 1
        for (int g = 0; g < 2; g++) {
            const int b0 = bb + g * 8;
            float acc[8][4];
#pragma unroll
            for (int i = 0; i < 8; i++) {
                acc[i][0] = 0.f; acc[i][1] = 0.f; acc[i][2] = 0.f; acc[i][3] = 0.f;
            }
#pragma unroll 1
            for (int ch = 0; ch < 1024; ch += 128) {
                const int ko = ch + (lane << 2);
                float4 uv0 = *(const float4*)&Us[(rw + 0) * 1024 + ko];
                float4 uv1 = *(const float4*)&Us[(rw + 1) * 1024 + ko];
                float4 uv2 = *(const float4*)&Us[(rw + 2) * 1024 + ko];
                float4 uv3 = *(const float4*)&Us[(rw + 3) * 1024 + ko];
#pragma unroll
                for (int i = 0; i < 8; i++) {
                    float4 hv = *(const float4*)&hs[(b0 + i) * 1024 + ko];
                    acc[i][0] = fmaf(hv.x, uv0.x, acc[i][0]);
                    acc[i][0] = fmaf(hv.y, uv0.y, acc[i][0]);
                    acc[i][0] = fmaf(hv.z, uv0.z, acc[i][0]);
                    acc[i][0] = fmaf(hv.w, uv0.w, acc[i][0]);
                    acc[i][1] = fmaf(hv.x, uv1.x, acc[i][1]);
                    acc[i][1] = fmaf(hv.y, uv1.y, acc[i][1]);
                    acc[i][1] = fmaf(hv.z, uv1.z, acc[i][1]);
                    acc[i][1] = fmaf(hv.w, uv1.w, acc[i][1]);
                    acc[i][2] = fmaf(hv.x, uv2.x, acc[i][2]);
                    acc[i][2] = fmaf(hv.y, uv2.y, acc[i][2]);
                    acc[i][2] = fmaf(hv.z, uv2.z, acc[i][2]);
                    acc[i][2] = fmaf(hv.w, uv2.w, acc[i][2]);
                    acc[i][3] = fmaf(hv.x, uv3.x, acc[i][3]);
                    acc[i][3] = fmaf(hv.y, uv3.y, acc[i][3]);
                    acc[i][3] = fmaf(hv.z, uv3.z, acc[i][3]);
                    acc[i][3] = fmaf(hv.w, uv3.w, acc[i][3]);
                }
            }
            // butterfly-reduce each output across lanes, scatter to SMEM
#pragma unroll
            for (int i = 0; i < 8; i++) {
#pragma unroll
                for (int j = 0; j < 4; j++) {
                    float v = acc[i][j];
                    v += __shfl_xor_sync(0xffffffffu, v, 16);
                    v += __shfl_xor_sync(0xffffffffu, v, 8);
                    v += __shfl_xor_sync(0xffffffffu, v, 4);
                    v += __shfl_xor_sync(0xffffffffu, v, 2);
                    v += __shfl_xor_sync(0xffffffffu, v, 1);
                    if (lane == (i * 4 + j)) uhs[(b0 + i) * 17 + rw + j] = v;
                }
            }
        }
        __syncthreads();

        // LN partial sums for this CTA's 16 features per batch row
        if (wid == 0) {
            float s = 0.f, ss = 0.f;
#pragma unroll
            for (int r = 0; r < 16; r++) {
                float v = uhs[lane * 17 + r];
                s += v;
                ss = fmaf(v, v, ss);
            }
            atomicAdd(&g_rowsum[par][lane], s);
            atomicAdd(&g_rowsumsq[par][lane], ss);
        }
        // one CTA zeroes the other parity's accumulators for the next step
        if (cid == 0 && wid == 1) {
            g_rowsum[1 - par][lane] = 0.f;
            g_rowsumsq[1 - par][lane] = 0.f;
        }

        grid_barrier((++epoch) * RGRID);

        // phase B: LN + gates + state update
        {
            float m = __ldcg(&g_rowsum[par][pb]) * (1.f / 2048.f);
            float ms = __ldcg(&g_rowsumsq[par][pb]) * (1.f / 2048.f);
            float inv = rsqrtf(ms - m * m + 1e-5f);
            float ga = fmaf(wa, scs[pj], bis[pj]) + (uhs[pb * 17 + pj] - m) * inv;
            float gz = fmaf(wz, scs[8 + pj], bis[8 + pj]) + (uhs[pb * 17 + 8 + pj] - m) * inv;
            float z = 1.f / (1.f + expf(-gz));
            float a = fmaxf(ga, 0.f);
            float hn = fmaf(z, hs[pb * 1024 + j0 + pj], (1.f - z) * a);
            g_h[pb * HH + j0 + pj] = hn;
            out[(pb * TT + t) * HH + j0 + pj] = hn;
        }

        grid_barrier((++epoch) * RGRID);
    }
}

// ---------------- launch ----------------
extern "C" void kernel_launch(void* const* d_in, const int* in_sizes, int n_in,
                              void* d_out, int out_size) {
    const float* x  = (const float*)d_in[0];
    const float* W1 = (const float*)d_in[1];
    const float* U1 = (const float*)d_in[2];
    const float* g1 = (const float*)d_in[3];
    const float* b1 = (const float*)d_in[4];
    const float* W2 = (const float*)d_in[5];
    const float* U2 = (const float*)d_in[6];
    const float* g2 = (const float*)d_in[7];
    const float* b2 = (const float*)d_in[8];
    float* out = (float*)d_out;

    const int RSMEM = (16 * 1024 + 32 * 1024 + 32 * 17 + 32) * 4;  // 198912 B
    cudaFuncSetAttribute(recurrence_kernel, cudaFuncAttributeMaxDynamicSharedMemorySize, RSMEM);

    // ---- layer 1 ----
    init_kernel<<<32, 1024>>>();
    proj_mma_kernel<<<dim3(16, 250), 256>>>(x, W1, 80, 0);
    bn_stats_kernel<<<dim3(8, 64), 256>>>();
    bn_finalize_kernel<<<8, 256>>>(g1, b1);
    recurrence_kernel<<<RGRID, RTHREADS, RSMEM>>>(U1, nullptr, 1);

    // ---- layer 2 ----
    init_kernel<<<32, 1024>>>();
    proj_mma_kernel<<<dim3(16, 250), 256>>>(nullptr, W2, 1024, 1);
    bn_stats_kernel<<<dim3(8, 64), 256>>>();
    bn_finalize_kernel<<<8, 256>>>(g2, b2);
    recurrence_kernel<<<RGRID, RTHREADS, RSMEM>>>(U2, out, 0);
}